// round 1
// baseline (speedup 1.0000x reference)
#include <cuda_runtime.h>
#include <math.h>

#define NB  16
#define SEQ 1024
#define DIM 1024
#define OFF2 ((size_t)NB * SEQ * 2048)

// Scratch (allocation-free rule: __device__ globals)
__device__ float g_E[(size_t)NB * SEQ * SEQ];   // exp(tanh(score)) : 64 MB
__device__ float g_u[NB * SEQ];
__device__ float g_v[NB * SEQ];
__device__ float g_rinv[NB * SEQ];              // 1/rowsum (softmax over r)
__device__ float g_cinv[NB * SEQ];              // 1/colsum (softmax over l)

// ---------------------------------------------------------------------------
// u[b,l] = lhs[b,l,:] . w[D:2D] ; v[b,r] = rhs[b,r,:] . w[2D:3D]
// ---------------------------------------------------------------------------
__global__ void uv_kernel(const float* __restrict__ lhs,
                          const float* __restrict__ rhs,
                          const float* __restrict__ w) {
  const int row = blockIdx.x;                       // 0 .. NB*SEQ-1
  const float* src = (blockIdx.y == 0) ? lhs : rhs;
  const float* wp  = w + ((blockIdx.y == 0) ? DIM : 2 * DIM);
  src += (size_t)row * DIM;
  const int k = threadIdx.x * 4;                    // 256 threads * 4 = 1024
  float4 a  = *(const float4*)(src + k);
  float4 ww = *(const float4*)(wp + k);
  float s = a.x * ww.x + a.y * ww.y + a.z * ww.z + a.w * ww.w;
  __shared__ float red[256];
  red[threadIdx.x] = s;
  __syncthreads();
  for (int o = 128; o > 0; o >>= 1) {
    if (threadIdx.x < o) red[threadIdx.x] += red[threadIdx.x + o];
    __syncthreads();
  }
  if (threadIdx.x == 0) {
    if (blockIdx.y == 0) g_u[row] = red[0];
    else                 g_v[row] = red[0];
  }
}

// ---------------------------------------------------------------------------
// score GEMM: S = (lhs .* w_prod) @ rhs^T  ; E = exp(tanh(S + u + v + bias))
// 128x128 block tile, 256 threads, 8x8 per thread, K-step 8.
// ---------------------------------------------------------------------------
__global__ __launch_bounds__(256) void score_kernel(
    const float* __restrict__ lhs, const float* __restrict__ rhs,
    const float* __restrict__ w, const float* __restrict__ bptr) {
  __shared__ float As[8][128];
  __shared__ float Bs[8][128];
  const int b  = blockIdx.z;
  const int i0 = blockIdx.y * 128;
  const int j0 = blockIdx.x * 128;
  const int tid = threadIdx.x;
  const int tx = tid & 15, ty = tid >> 4;
  const int lr = tid >> 1, lk = (tid & 1) * 4;

  const float* Ap = lhs + ((size_t)b * SEQ + i0 + lr) * DIM + lk;
  const float* Bp = rhs + ((size_t)b * SEQ + j0 + lr) * DIM + lk;

  float acc[8][8];
#pragma unroll
  for (int m = 0; m < 8; m++)
#pragma unroll
    for (int n = 0; n < 8; n++) acc[m][n] = 0.f;

  for (int k0 = 0; k0 < DIM; k0 += 8) {
    float4 a  = *(const float4*)(Ap + k0);
    float4 bb = *(const float4*)(Bp + k0);
    float4 ww = *(const float4*)(w + k0 + lk);   // w_prod slice
    As[lk + 0][lr] = a.x * ww.x;
    As[lk + 1][lr] = a.y * ww.y;
    As[lk + 2][lr] = a.z * ww.z;
    As[lk + 3][lr] = a.w * ww.w;
    Bs[lk + 0][lr] = bb.x;
    Bs[lk + 1][lr] = bb.y;
    Bs[lk + 2][lr] = bb.z;
    Bs[lk + 3][lr] = bb.w;
    __syncthreads();
#pragma unroll
    for (int k = 0; k < 8; k++) {
      float4 a0 = *(const float4*)&As[k][ty * 4];
      float4 a1 = *(const float4*)&As[k][64 + ty * 4];
      float4 b0 = *(const float4*)&Bs[k][tx * 4];
      float4 b1 = *(const float4*)&Bs[k][64 + tx * 4];
      float af[8] = {a0.x, a0.y, a0.z, a0.w, a1.x, a1.y, a1.z, a1.w};
      float bf[8] = {b0.x, b0.y, b0.z, b0.w, b1.x, b1.y, b1.z, b1.w};
#pragma unroll
      for (int m = 0; m < 8; m++)
#pragma unroll
        for (int n = 0; n < 8; n++) acc[m][n] += af[m] * bf[n];
    }
    __syncthreads();
  }

  const float bias = *bptr;
  float vv[8];
#pragma unroll
  for (int n = 0; n < 8; n++) {
    int cj = j0 + ((n < 4) ? (tx * 4 + n) : (64 + tx * 4 + n - 4));
    vv[n] = g_v[b * SEQ + cj];
  }
#pragma unroll
  for (int m = 0; m < 8; m++) {
    int ri = i0 + ((m < 4) ? (ty * 4 + m) : (64 + ty * 4 + m - 4));
    float um = g_u[b * SEQ + ri] + bias;
    float* erow = g_E + ((size_t)b * SEQ + ri) * SEQ + j0;
    float4 o0, o1;
    o0.x = __expf(tanhf(acc[m][0] + um + vv[0]));
    o0.y = __expf(tanhf(acc[m][1] + um + vv[1]));
    o0.z = __expf(tanhf(acc[m][2] + um + vv[2]));
    o0.w = __expf(tanhf(acc[m][3] + um + vv[3]));
    o1.x = __expf(tanhf(acc[m][4] + um + vv[4]));
    o1.y = __expf(tanhf(acc[m][5] + um + vv[5]));
    o1.z = __expf(tanhf(acc[m][6] + um + vv[6]));
    o1.w = __expf(tanhf(acc[m][7] + um + vv[7]));
    *(float4*)(erow + tx * 4)      = o0;
    *(float4*)(erow + 64 + tx * 4) = o1;
  }
}

// ---------------------------------------------------------------------------
// rowsum / colsum -> reciprocals
// ---------------------------------------------------------------------------
__global__ void rowsum_kernel() {
  const size_t row = blockIdx.x;
  const float* e = g_E + row * SEQ;
  const int j = threadIdx.x * 4;
  float4 v = *(const float4*)(e + j);
  float s = v.x + v.y + v.z + v.w;
  __shared__ float red[256];
  red[threadIdx.x] = s;
  __syncthreads();
  for (int o = 128; o > 0; o >>= 1) {
    if (threadIdx.x < o) red[threadIdx.x] += red[threadIdx.x + o];
    __syncthreads();
  }
  if (threadIdx.x == 0) g_rinv[row] = 1.0f / red[0];
}

__global__ void colsum_kernel() {
  const int b = blockIdx.y;
  const int r = blockIdx.x * 256 + threadIdx.x;
  const float* e = g_E + (size_t)b * SEQ * SEQ + r;
  float s = 0.f;
#pragma unroll 4
  for (int l = 0; l < SEQ; l++) s += e[(size_t)l * SEQ];
  g_cinv[b * SEQ + r] = 1.0f / s;
}

// ---------------------------------------------------------------------------
// MODE 0: C = (E / rowsum) @ rhs      -> lhs_out[:, :, 1024:2048]
// MODE 1: C = (E^T / colsum) @ lhs    -> rhs_out[:, :, 1024:2048]
// ---------------------------------------------------------------------------
template <int MODE>
__global__ __launch_bounds__(256) void av_kernel(const float* __restrict__ Bm,
                                                 float* __restrict__ out) {
  __shared__ float As[8][128];
  __shared__ float Bs[8][128];
  const int b  = blockIdx.z;
  const int i0 = blockIdx.y * 128;
  const int j0 = blockIdx.x * 128;
  const int tid = threadIdx.x;
  const int tx = tid & 15, ty = tid >> 4;
  const int bk = tid >> 5;            // 0..7
  const int bj = (tid & 31) * 4;      // 0..124

  const float* Eb = g_E + (size_t)b * SEQ * SEQ;
  const float* Bb = Bm + (size_t)b * SEQ * DIM;

  float acc[8][8];
#pragma unroll
  for (int m = 0; m < 8; m++)
#pragma unroll
    for (int n = 0; n < 8; n++) acc[m][n] = 0.f;

  for (int k0 = 0; k0 < SEQ; k0 += 8) {
    if (MODE == 0) {
      const int lr = tid >> 1, lk = (tid & 1) * 4;
      float4 a = *(const float4*)(Eb + (size_t)(i0 + lr) * SEQ + k0 + lk);
      As[lk + 0][lr] = a.x;
      As[lk + 1][lr] = a.y;
      As[lk + 2][lr] = a.z;
      As[lk + 3][lr] = a.w;
    } else {
      float4 a = *(const float4*)(Eb + (size_t)(k0 + bk) * SEQ + i0 + bj);
      *(float4*)&As[bk][bj] = a;
    }
    float4 bb = *(const float4*)(Bb + (size_t)(k0 + bk) * DIM + j0 + bj);
    *(float4*)&Bs[bk][bj] = bb;
    __syncthreads();
#pragma unroll
    for (int k = 0; k < 8; k++) {
      float4 a0 = *(const float4*)&As[k][ty * 4];
      float4 a1 = *(const float4*)&As[k][64 + ty * 4];
      float4 b0 = *(const float4*)&Bs[k][tx * 4];
      float4 b1 = *(const float4*)&Bs[k][64 + tx * 4];
      float af[8] = {a0.x, a0.y, a0.z, a0.w, a1.x, a1.y, a1.z, a1.w};
      float bf[8] = {b0.x, b0.y, b0.z, b0.w, b1.x, b1.y, b1.z, b1.w};
#pragma unroll
      for (int m = 0; m < 8; m++)
#pragma unroll
        for (int n = 0; n < 8; n++) acc[m][n] += af[m] * bf[n];
    }
    __syncthreads();
  }

#pragma unroll
  for (int m = 0; m < 8; m++) {
    int ri = i0 + ((m < 4) ? (ty * 4 + m) : (64 + ty * 4 + m - 4));
    float inv = (MODE == 0 ? g_rinv : g_cinv)[b * SEQ + ri];
    float* orow = out + ((size_t)b * SEQ + ri) * 2048 + 1024 + j0;
    float4 o0 = make_float4(acc[m][0] * inv, acc[m][1] * inv,
                            acc[m][2] * inv, acc[m][3] * inv);
    float4 o1 = make_float4(acc[m][4] * inv, acc[m][5] * inv,
                            acc[m][6] * inv, acc[m][7] * inv);
    *(float4*)(orow + tx * 4)      = o0;
    *(float4*)(orow + 64 + tx * 4) = o1;
  }
}

// ---------------------------------------------------------------------------
// Identity halves: out[b,x,0:1024] = src[b,x,:]
// ---------------------------------------------------------------------------
__global__ void copy_kernel(const float4* __restrict__ src,
                            float4* __restrict__ dst) {
  size_t i = (size_t)blockIdx.x * blockDim.x + threadIdx.x;  // 4,194,304 total
  size_t row = i >> 8;   // 256 float4 per source row
  size_t c   = i & 255;
  dst[row * 512 + c] = src[i];
}

// ---------------------------------------------------------------------------
extern "C" void kernel_launch(void* const* d_in, const int* in_sizes, int n_in,
                              void* d_out, int out_size) {
  const float* lhs = (const float*)d_in[0];
  const float* rhs = (const float*)d_in[1];
  const float* w   = (const float*)d_in[2];
  const float* bp  = (const float*)d_in[3];
  float* out = (float*)d_out;

  uv_kernel<<<dim3(NB * SEQ, 2), 256>>>(lhs, rhs, w);
  score_kernel<<<dim3(8, 8, NB), 256>>>(lhs, rhs, w, bp);
  rowsum_kernel<<<NB * SEQ, 256>>>();
  colsum_kernel<<<dim3(SEQ / 256, NB), 256>>>();
  av_kernel<0><<<dim3(8, 8, NB), 256>>>(rhs, out);
  av_kernel<1><<<dim3(8, 8, NB), 256>>>(lhs, out + OFF2);
  copy_kernel<<<16384, 256>>>((const float4*)lhs, (float4*)out);
  copy_kernel<<<16384, 256>>>((const float4*)rhs, (float4*)(out + OFF2));
}

// round 8
// speedup vs baseline: 4.6858x; 4.6858x over previous
#include <cuda_runtime.h>
#include <cuda_fp16.h>
#include <mma.h>
#include <math.h>
#include <stdint.h>

using namespace nvcuda;

#define NB  16
#define SEQ 1024
#define DIM 1024
#define OFF2 ((size_t)NB * SEQ * 2048)

// ---------------------------------------------------------------------------
// Scratch (__device__ globals; allocation-free rule)
// ---------------------------------------------------------------------------
__device__ __align__(256) __half g_aH[(size_t)NB * SEQ * DIM];  // fp16(lhs * w_prod)
__device__ __align__(256) __half g_lH[(size_t)NB * SEQ * DIM];  // fp16(lhs)
__device__ __align__(256) __half g_rH[(size_t)NB * SEQ * DIM];  // fp16(rhs)
__device__ __align__(256) __half g_E [(size_t)NB * SEQ * SEQ];  // exp(tanh(score)) [b][l][r]
__device__ float g_u[NB * SEQ];
__device__ float g_v[NB * SEQ];
__device__ float g_rinv[NB * SEQ];          // 1 / rowsum(E)  (softmax over r)
__device__ float g_cinv[NB * SEQ];          // 1 / colsum(E)  (softmax over l)
__device__ float g_cpart[NB * 8 * SEQ];     // colsum partials

// ---------------------------------------------------------------------------
// PTX helpers (compute_103-safe)
// ---------------------------------------------------------------------------
__device__ __forceinline__ uint32_t smem_u32(const void* p) {
  uint32_t a;
  asm("{ .reg .u64 t; cvta.to.shared.u64 t, %1; cvt.u32.u64 %0, t; }"
      : "=r"(a) : "l"(p));
  return a;
}
__device__ __forceinline__ void cp_async16(uint32_t dst, const void* src) {
  asm volatile("cp.async.cg.shared.global [%0], [%1], 16;"
               :: "r"(dst), "l"(src) : "memory");
}
template <int N> __device__ __forceinline__ void cp_wait() {
  asm volatile("cp.async.wait_group %0;" :: "n"(N) : "memory");
}
__device__ __forceinline__ void cp_commit() {
  asm volatile("cp.async.commit_group;" ::: "memory");
}

// ---------------------------------------------------------------------------
// prep: aH = fp16(lhs*w_prod), lH = fp16(lhs), rH = fp16(rhs)
// ---------------------------------------------------------------------------
__global__ void prep_kernel(const float4* __restrict__ lhs,
                            const float4* __restrict__ rhs,
                            const float4* __restrict__ w) {
  size_t i = (size_t)blockIdx.x * blockDim.x + threadIdx.x;   // 4M float4
  float4 x = lhs[i];
  float4 y = rhs[i];
  float4 ww = w[i & 255];                  // w_prod float4 per 1024-elem row
  __half2* aH2 = (__half2*)g_aH;
  __half2* lH2 = (__half2*)g_lH;
  __half2* rH2 = (__half2*)g_rH;
  aH2[2 * i]     = __floats2half2_rn(x.x * ww.x, x.y * ww.y);
  aH2[2 * i + 1] = __floats2half2_rn(x.z * ww.z, x.w * ww.w);
  lH2[2 * i]     = __floats2half2_rn(x.x, x.y);
  lH2[2 * i + 1] = __floats2half2_rn(x.z, x.w);
  rH2[2 * i]     = __floats2half2_rn(y.x, y.y);
  rH2[2 * i + 1] = __floats2half2_rn(y.z, y.w);
}

// ---------------------------------------------------------------------------
// u[b,l] = lhs[b,l,:] . w[D:2D] ; v[b,r] = rhs[b,r,:] . w[2D:3D]  (fp32)
// (proven in round 1)
// ---------------------------------------------------------------------------
__global__ void uv_kernel(const float* __restrict__ lhs,
                          const float* __restrict__ rhs,
                          const float* __restrict__ w) {
  const int row = blockIdx.x;
  const float* src = (blockIdx.y == 0) ? lhs : rhs;
  const float* wp  = w + ((blockIdx.y == 0) ? DIM : 2 * DIM);
  src += (size_t)row * DIM;
  const int k = threadIdx.x * 4;
  float4 a  = *(const float4*)(src + k);
  float4 ww = *(const float4*)(wp + k);
  float s = a.x * ww.x + a.y * ww.y + a.z * ww.z + a.w * ww.w;
  __shared__ float red[256];
  red[threadIdx.x] = s;
  __syncthreads();
  for (int o = 128; o > 0; o >>= 1) {
    if (threadIdx.x < o) red[threadIdx.x] += red[threadIdx.x + o];
    __syncthreads();
  }
  if (threadIdx.x == 0) {
    if (blockIdx.y == 0) g_u[row] = red[0];
    else                 g_v[row] = red[0];
  }
}

// ---------------------------------------------------------------------------
// wmma GEMM, 128x128 CTA tile, K=1024, fp16 in / fp32 acc. NO pre-transposed
// operands: transposition is expressed via wmma row/col-major fragments.
//   MODE 0: C[l][r] = sum_d aH[l][d]*rH[r][d]   (A row_major NK, B col_major NK)
//           -> E = fp16(exp(tanh(C + u[l] + v[r] + bias)))
//   MODE 1: C[l][d] = sum_r E[l][r]*rH[r][d]    (A row_major NK, B row_major KN)
//           -> out[l, 1024+d] = C * rinv[l]
//   MODE 2: C[r][d] = sum_l E[l][r]*lH[l][d]    (A col_major KN, B row_major KN)
//           -> out[r, 1024+d] = C * cinv[r]
// NK tile: 128 rows x 64 halves, row stride 72 halves (144B).
// KN tile:  64 rows x 128 halves, row stride 136 halves (272B).
// ---------------------------------------------------------------------------
#define STAGEB  36864                    // A-sect 18432 + B-sect 18432
#define GSMEM   (2 * STAGEB)             // 73728 (epilogue reuses 64KB of it)

template <int MODE>
__global__ __launch_bounds__(256) void mma_gemm(const float* __restrict__ bias,
                                                float* __restrict__ out) {
  extern __shared__ char smem[];
  const uint32_t sb = smem_u32(smem);
  const int tid = threadIdx.x, wid = tid >> 5;
  const int b = blockIdx.z, i0 = blockIdx.y * 128, j0 = blockIdx.x * 128;
  const int wm = (wid & 3) * 32;    // warp m offset
  const int wn = (wid >> 2) * 64;   // warp n offset

  constexpr bool A_NK = (MODE <= 1);
  constexpr bool B_NK = (MODE == 0);

  const __half* Asrc =
      (MODE == 0) ? g_aH + ((size_t)b * SEQ + i0) * 1024
    : (MODE == 1) ? g_E  + ((size_t)b * SEQ + i0) * 1024
                  : g_E  + (size_t)b * SEQ * SEQ;            // KN: cols i0
  const __half* Bsrc =
      (MODE == 0) ? g_rH + ((size_t)b * SEQ + j0) * 1024
    : (MODE == 1) ? g_rH + (size_t)b * SEQ * 1024            // KN: cols j0
                  : g_lH + (size_t)b * SEQ * 1024;           // KN: cols j0

  wmma::fragment<wmma::accumulator, 16, 16, 16, float> c[2][4];
#pragma unroll
  for (int mt = 0; mt < 2; mt++)
#pragma unroll
    for (int nt = 0; nt < 4; nt++) wmma::fill_fragment(c[mt][nt], 0.0f);

#define ISSUE(k0, s)                                                          \
  do {                                                                        \
    uint32_t ab_ = sb + (s) * STAGEB;                                         \
    uint32_t bb_ = ab_ + 18432;                                               \
    _Pragma("unroll")                                                         \
    for (int q = 0; q < 4; q++) {                                             \
      int idx_ = q * 256 + tid;                                               \
      if (A_NK) {                                                             \
        int row_ = idx_ >> 3, c_ = idx_ & 7;                                  \
        cp_async16(ab_ + row_ * 144 + c_ * 16,                                \
                   Asrc + (size_t)row_ * 1024 + (k0) + c_ * 8);               \
      } else {                                                                \
        int row_ = idx_ >> 4, c_ = idx_ & 15;                                 \
        cp_async16(ab_ + row_ * 272 + c_ * 16,                                \
                   Asrc + (size_t)((k0) + row_) * 1024 + i0 + c_ * 8);        \
      }                                                                       \
      if (B_NK) {                                                             \
        int row_ = idx_ >> 3, c_ = idx_ & 7;                                  \
        cp_async16(bb_ + row_ * 144 + c_ * 16,                                \
                   Bsrc + (size_t)row_ * 1024 + (k0) + c_ * 8);               \
      } else {                                                                \
        int row_ = idx_ >> 4, c_ = idx_ & 15;                                 \
        cp_async16(bb_ + row_ * 272 + c_ * 16,                                \
                   Bsrc + (size_t)((k0) + row_) * 1024 + j0 + c_ * 8);        \
      }                                                                       \
    }                                                                         \
    cp_commit();                                                              \
  } while (0)

  ISSUE(0, 0);
#pragma unroll 1
  for (int ch = 0; ch < 16; ++ch) {
    const int buf = ch & 1;
    if (ch < 15) { ISSUE((ch + 1) * 64, buf ^ 1); cp_wait<1>(); }
    else         { cp_wait<0>(); }
    __syncthreads();

    const __half* As = (const __half*)(smem + buf * STAGEB);
    const __half* Bs = (const __half*)(smem + buf * STAGEB + 18432);
#pragma unroll
    for (int ks = 0; ks < 4; ++ks) {
      const int kk = ks * 16;
      if constexpr (A_NK && B_NK) {            // MODE 0
        wmma::fragment<wmma::matrix_a, 16, 16, 16, __half, wmma::row_major> af[2];
#pragma unroll
        for (int mt = 0; mt < 2; mt++)
          wmma::load_matrix_sync(af[mt], As + (wm + mt * 16) * 72 + kk, 72);
#pragma unroll
        for (int nt = 0; nt < 4; nt++) {
          wmma::fragment<wmma::matrix_b, 16, 16, 16, __half, wmma::col_major> bf;
          wmma::load_matrix_sync(bf, Bs + (wn + nt * 16) * 72 + kk, 72);
          wmma::mma_sync(c[0][nt], af[0], bf, c[0][nt]);
          wmma::mma_sync(c[1][nt], af[1], bf, c[1][nt]);
        }
      } else if constexpr (A_NK && !B_NK) {    // MODE 1
        wmma::fragment<wmma::matrix_a, 16, 16, 16, __half, wmma::row_major> af[2];
#pragma unroll
        for (int mt = 0; mt < 2; mt++)
          wmma::load_matrix_sync(af[mt], As + (wm + mt * 16) * 72 + kk, 72);
#pragma unroll
        for (int nt = 0; nt < 4; nt++) {
          wmma::fragment<wmma::matrix_b, 16, 16, 16, __half, wmma::row_major> bf;
          wmma::load_matrix_sync(bf, Bs + kk * 136 + wn + nt * 16, 136);
          wmma::mma_sync(c[0][nt], af[0], bf, c[0][nt]);
          wmma::mma_sync(c[1][nt], af[1], bf, c[1][nt]);
        }
      } else {                                 // MODE 2
        wmma::fragment<wmma::matrix_a, 16, 16, 16, __half, wmma::col_major> af[2];
#pragma unroll
        for (int mt = 0; mt < 2; mt++)
          wmma::load_matrix_sync(af[mt], As + kk * 136 + wm + mt * 16, 136);
#pragma unroll
        for (int nt = 0; nt < 4; nt++) {
          wmma::fragment<wmma::matrix_b, 16, 16, 16, __half, wmma::row_major> bf;
          wmma::load_matrix_sync(bf, Bs + kk * 136 + wn + nt * 16, 136);
          wmma::mma_sync(c[0][nt], af[0], bf, c[0][nt]);
          wmma::mma_sync(c[1][nt], af[1], bf, c[1][nt]);
        }
      }
    }
    __syncthreads();
  }
#undef ISSUE

  // ---- stage accumulators to SMEM (compiler-owned layout), plain epilogue
  float* sf = (float*)smem;                 // 128x128 f32 = 64KB
#pragma unroll
  for (int mt = 0; mt < 2; mt++)
#pragma unroll
    for (int nt = 0; nt < 4; nt++)
      wmma::store_matrix_sync(sf + (size_t)(wm + mt * 16) * 128 + wn + nt * 16,
                              c[mt][nt], 128, wmma::mem_row_major);
  __syncthreads();

  const int r = tid >> 1;                   // 0..127
  const int chalf = (tid & 1) * 64;         // 0 or 64
  const int ri = i0 + r;
  const float* srow = sf + (size_t)r * 128 + chalf;

  if (MODE == 0) {
    const float u0 = g_u[b * SEQ + ri] + bias[0];
    __half* erow = g_E + ((size_t)b * SEQ + ri) * 1024 + j0 + chalf;
#pragma unroll
    for (int q = 0; q < 16; ++q) {
      float4 s4 = *(const float4*)(srow + q * 4);
      const int col = j0 + chalf + q * 4;
      float e0 = __expf(tanhf(s4.x + u0 + g_v[b * SEQ + col]));
      float e1 = __expf(tanhf(s4.y + u0 + g_v[b * SEQ + col + 1]));
      float e2 = __expf(tanhf(s4.z + u0 + g_v[b * SEQ + col + 2]));
      float e3 = __expf(tanhf(s4.w + u0 + g_v[b * SEQ + col + 3]));
      *(__half2*)(erow + q * 4)     = __floats2half2_rn(e0, e1);
      *(__half2*)(erow + q * 4 + 2) = __floats2half2_rn(e2, e3);
    }
  } else {
    const float* scale = (MODE == 1) ? g_rinv : g_cinv;
    const float iv = scale[b * SEQ + ri];
    float4* orow = (float4*)(out + ((size_t)b * SEQ + ri) * 2048 + 1024 + j0 + chalf);
#pragma unroll
    for (int q = 0; q < 16; ++q) {
      float4 s4 = *(const float4*)(srow + q * 4);
      orow[q] = make_float4(s4.x * iv, s4.y * iv, s4.z * iv, s4.w * iv);
    }
  }
}

// ---------------------------------------------------------------------------
// rowsum(E) -> g_rinv. One warp per row (coalesced).
// ---------------------------------------------------------------------------
__global__ void sumrows_kernel() {
  const int row = blockIdx.x * 8 + (threadIdx.x >> 5);
  const int lane = threadIdx.x & 31;
  const uint4* p = (const uint4*)(g_E + (size_t)row * 1024);
  float s = 0.f;
#pragma unroll
  for (int q = 0; q < 4; ++q) {
    uint4 v = p[lane + q * 32];
    __half2 h[4];
    *(uint4*)h = v;
#pragma unroll
    for (int j = 0; j < 4; ++j) {
      float2 f = __half22float2(h[j]);
      s += f.x + f.y;
    }
  }
#pragma unroll
  for (int o = 16; o > 0; o >>= 1) s += __shfl_xor_sync(0xffffffff, s, o);
  if (lane == 0) g_rinv[row] = 1.0f / s;
}

// ---------------------------------------------------------------------------
// colsum(E) two-stage: partials over 128-row chunks, then combine -> g_cinv
// ---------------------------------------------------------------------------
__global__ void colsum_part() {
  const int b = blockIdx.z, chunk = blockIdx.y;
  const int r = blockIdx.x * 256 + threadIdx.x;
  const __half* e = g_E + (size_t)b * SEQ * SEQ + (size_t)chunk * 128 * SEQ + r;
  float s = 0.f;
#pragma unroll 8
  for (int l = 0; l < 128; l++) s += __half2float(e[(size_t)l * SEQ]);
  g_cpart[(b * 8 + chunk) * SEQ + r] = s;
}
__global__ void colsum_fin() {
  const int idx = blockIdx.x * 256 + threadIdx.x;   // b*SEQ + r
  const int b = idx >> 10, r = idx & 1023;
  float s = 0.f;
#pragma unroll
  for (int c = 0; c < 8; c++) s += g_cpart[(b * 8 + c) * SEQ + r];
  g_cinv[idx] = 1.0f / s;
}

// ---------------------------------------------------------------------------
// Identity halves: out[b,x,0:1024] = src[b,x,:]   (proven in round 1)
// ---------------------------------------------------------------------------
__global__ void copy_kernel(const float4* __restrict__ src,
                            float4* __restrict__ dst) {
  size_t i = (size_t)blockIdx.x * blockDim.x + threadIdx.x;
  size_t row = i >> 8;
  size_t c = i & 255;
  dst[row * 512 + c] = src[i];
}

// ---------------------------------------------------------------------------
extern "C" void kernel_launch(void* const* d_in, const int* in_sizes, int n_in,
                              void* d_out, int out_size) {
  const float* lhs = (const float*)d_in[0];
  const float* rhs = (const float*)d_in[1];
  const float* w   = (const float*)d_in[2];
  const float* bp  = (const float*)d_in[3];
  float* out = (float*)d_out;

  cudaFuncSetAttribute(mma_gemm<0>, cudaFuncAttributeMaxDynamicSharedMemorySize, GSMEM);
  cudaFuncSetAttribute(mma_gemm<1>, cudaFuncAttributeMaxDynamicSharedMemorySize, GSMEM);
  cudaFuncSetAttribute(mma_gemm<2>, cudaFuncAttributeMaxDynamicSharedMemorySize, GSMEM);

  prep_kernel<<<16384, 256>>>((const float4*)lhs, (const float4*)rhs, (const float4*)w);
  uv_kernel<<<dim3(NB * SEQ, 2), 256>>>(lhs, rhs, w);

  mma_gemm<0><<<dim3(8, 8, NB), 256, GSMEM>>>(bp, out);        // -> g_E
  sumrows_kernel<<<NB * SEQ / 8, 256>>>();                      // rinv
  colsum_part<<<dim3(4, 8, NB), 256>>>();
  colsum_fin<<<NB * SEQ / 256, 256>>>();                        // cinv

  mma_gemm<1><<<dim3(8, 8, NB), 256, GSMEM>>>(bp, out);         // lhs attn
  mma_gemm<2><<<dim3(8, 8, NB), 256, GSMEM>>>(bp, out + OFF2);  // rhs attn

  copy_kernel<<<16384, 256>>>((const float4*)lhs, (float4*)out);
  copy_kernel<<<16384, 256>>>((const float4*)rhs, (float4*)(out + OFF2));
}

// round 9
// speedup vs baseline: 5.2863x; 1.1282x over previous
#include <cuda_runtime.h>
#include <cuda_fp16.h>
#include <mma.h>
#include <math.h>
#include <stdint.h>

using namespace nvcuda;

#define NB  16
#define SEQ 1024
#define DIM 1024
#define OFF2 ((size_t)NB * SEQ * 2048)

// ---------------------------------------------------------------------------
// Scratch (__device__ globals; allocation-free rule)
// ---------------------------------------------------------------------------
__device__ __align__(256) __half g_aH[(size_t)NB * SEQ * DIM];  // fp16(lhs * w_prod)
__device__ __align__(256) __half g_lH[(size_t)NB * SEQ * DIM];  // fp16(lhs)
__device__ __align__(256) __half g_rH[(size_t)NB * SEQ * DIM];  // fp16(rhs)
__device__ __align__(256) __half g_E [(size_t)NB * SEQ * SEQ];  // exp(tanh(score)) [b][l][r]
__device__ float g_u[NB * SEQ];
__device__ float g_v[NB * SEQ];
__device__ float g_rinv[NB * SEQ];          // 1 / rowsum(E)
__device__ float g_cinv[NB * SEQ];          // 1 / colsum(E)
__device__ float g_rpart[8 * NB * SEQ];     // rowsum partials (per j-tile)
__device__ float g_cpart[NB * 8 * SEQ];     // colsum partials (per l-chunk)

// ---------------------------------------------------------------------------
// PTX helpers (compute_103-safe)
// ---------------------------------------------------------------------------
__device__ __forceinline__ uint32_t smem_u32(const void* p) {
  uint32_t a;
  asm("{ .reg .u64 t; cvta.to.shared.u64 t, %1; cvt.u32.u64 %0, t; }"
      : "=r"(a) : "l"(p));
  return a;
}
__device__ __forceinline__ void cp_async16(uint32_t dst, const void* src) {
  asm volatile("cp.async.cg.shared.global [%0], [%1], 16;"
               :: "r"(dst), "l"(src) : "memory");
}
template <int N> __device__ __forceinline__ void cp_wait() {
  asm volatile("cp.async.wait_group %0;" :: "n"(N) : "memory");
}
__device__ __forceinline__ void cp_commit() {
  asm volatile("cp.async.commit_group;" ::: "memory");
}

// ---------------------------------------------------------------------------
// fuse: one pass over lhs/rhs does
//   aH = fp16(lhs*w_prod), lH = fp16(lhs), rH = fp16(rhs)
//   out identity halves: out[b,l,0:1024]=lhs, out2[b,r,0:1024]=rhs
//   u[row] = lhs row . w_l ; v[row] = rhs row . w_r
// One block per row pair (block row covers exactly 256 float4 = 1024 elems).
// ---------------------------------------------------------------------------
__global__ __launch_bounds__(256) void fuse_kernel(
    const float4* __restrict__ lhs, const float4* __restrict__ rhs,
    const float4* __restrict__ w, float4* __restrict__ out) {
  const int row = blockIdx.x;                 // 0..16383 = b*1024 + x
  const int t = threadIdx.x;
  const size_t i = (size_t)row * 256 + t;

  float4 x = lhs[i];
  float4 y = rhs[i];
  float4 wp = w[t];
  float4 wl = w[256 + t];
  float4 wr = w[512 + t];

  // identity halves (out rows are 2048 floats = 512 float4)
  out[(size_t)row * 512 + t] = x;
  out[OFF2 / 4 + (size_t)row * 512 + t] = y;

  // fp16 operands
  __half2* aH2 = (__half2*)g_aH;
  __half2* lH2 = (__half2*)g_lH;
  __half2* rH2 = (__half2*)g_rH;
  aH2[2 * i]     = __floats2half2_rn(x.x * wp.x, x.y * wp.y);
  aH2[2 * i + 1] = __floats2half2_rn(x.z * wp.z, x.w * wp.w);
  lH2[2 * i]     = __floats2half2_rn(x.x, x.y);
  lH2[2 * i + 1] = __floats2half2_rn(x.z, x.w);
  rH2[2 * i]     = __floats2half2_rn(y.x, y.y);
  rH2[2 * i + 1] = __floats2half2_rn(y.z, y.w);

  // u / v reductions (round-1-proven tree)
  __shared__ float red[512];
  red[t]       = x.x * wl.x + x.y * wl.y + x.z * wl.z + x.w * wl.w;
  red[256 + t] = y.x * wr.x + y.y * wr.y + y.z * wr.z + y.w * wr.w;
  __syncthreads();
  for (int o = 128; o > 0; o >>= 1) {
    if (t < o) {
      red[t] += red[t + o];
      red[256 + t] += red[256 + t + o];
    }
    __syncthreads();
  }
  if (t == 0) {
    g_u[row] = red[0];
    g_v[row] = red[256];
  }
}

// ---------------------------------------------------------------------------
// wmma GEMM, 128x128 CTA tile, K=1024, fp16 in / fp32 acc. 3-stage cp.async.
//   MODE 0: C[l][r] = sum_d aH[l][d]*rH[r][d]   (A row_major NK, B col_major NK)
//           -> E = fp16(exp(tanh(C + u[l] + v[r] + bias))) ; rowsum partials
//   MODE 1: C[l][d] = sum_r E[l][r]*rH[r][d]    (A row_major NK, B row_major KN)
//           -> out[l, 1024+d] = C * rinv[l]
//   MODE 2: C[r][d] = sum_l E[l][r]*lH[l][d]    (A col_major KN, B row_major KN)
//           -> out[r, 1024+d] = C * cinv[r]
// NK tile: 128 rows x 64 halves, stride 72 halves. KN tile: 64 x 128, stride 136.
// ---------------------------------------------------------------------------
#define STAGEB  36864                    // A-sect 18432 + B-sect 18432
#define GSMEM   (3 * STAGEB)             // 110592; epilogue reuses 64KB of it

template <int MODE>
__global__ __launch_bounds__(256) void mma_gemm(const float* __restrict__ bias,
                                                float* __restrict__ out) {
  extern __shared__ char smem[];
  const uint32_t sb = smem_u32(smem);
  const int tid = threadIdx.x, wid = tid >> 5;
  const int b = blockIdx.z, i0 = blockIdx.y * 128, j0 = blockIdx.x * 128;
  const int wm = (wid & 3) * 32;
  const int wn = (wid >> 2) * 64;

  constexpr bool A_NK = (MODE <= 1);
  constexpr bool B_NK = (MODE == 0);

  const __half* Asrc =
      (MODE == 0) ? g_aH + ((size_t)b * SEQ + i0) * 1024
    : (MODE == 1) ? g_E  + ((size_t)b * SEQ + i0) * 1024
                  : g_E  + (size_t)b * SEQ * SEQ;            // KN: cols i0
  const __half* Bsrc =
      (MODE == 0) ? g_rH + ((size_t)b * SEQ + j0) * 1024
    : (MODE == 1) ? g_rH + (size_t)b * SEQ * 1024            // KN: cols j0
                  : g_lH + (size_t)b * SEQ * 1024;           // KN: cols j0

  wmma::fragment<wmma::accumulator, 16, 16, 16, float> c[2][4];
#pragma unroll
  for (int mt = 0; mt < 2; mt++)
#pragma unroll
    for (int nt = 0; nt < 4; nt++) wmma::fill_fragment(c[mt][nt], 0.0f);

#define ISSUE(k0, s)                                                          \
  do {                                                                        \
    uint32_t ab_ = sb + (s) * STAGEB;                                         \
    uint32_t bb_ = ab_ + 18432;                                               \
    _Pragma("unroll")                                                         \
    for (int q = 0; q < 4; q++) {                                             \
      int idx_ = q * 256 + tid;                                               \
      if (A_NK) {                                                             \
        int row_ = idx_ >> 3, c_ = idx_ & 7;                                  \
        cp_async16(ab_ + row_ * 144 + c_ * 16,                                \
                   Asrc + (size_t)row_ * 1024 + (k0) + c_ * 8);               \
      } else {                                                                \
        int row_ = idx_ >> 4, c_ = idx_ & 15;                                 \
        cp_async16(ab_ + row_ * 272 + c_ * 16,                                \
                   Asrc + (size_t)((k0) + row_) * 1024 + i0 + c_ * 8);        \
      }                                                                       \
      if (B_NK) {                                                             \
        int row_ = idx_ >> 3, c_ = idx_ & 7;                                  \
        cp_async16(bb_ + row_ * 144 + c_ * 16,                                \
                   Bsrc + (size_t)row_ * 1024 + (k0) + c_ * 8);               \
      } else {                                                                \
        int row_ = idx_ >> 4, c_ = idx_ & 15;                                 \
        cp_async16(bb_ + row_ * 272 + c_ * 16,                                \
                   Bsrc + (size_t)((k0) + row_) * 1024 + j0 + c_ * 8);        \
      }                                                                       \
    }                                                                         \
    cp_commit();                                                              \
  } while (0)

  ISSUE(0, 0);
  ISSUE(64, 1);
#pragma unroll 1
  for (int ch = 0; ch < 16; ++ch) {
    cp_wait<1>();            // commit #ch (= chunk ch) retired
    __syncthreads();         // data visible + all warps done with chunk ch-1
    if (ch + 2 < 16) ISSUE((ch + 2) * 64, (ch + 2) % 3);
    else             cp_commit();            // keep group count uniform

    const int buf = ch % 3;
    const __half* As = (const __half*)(smem + buf * STAGEB);
    const __half* Bs = (const __half*)(smem + buf * STAGEB + 18432);
#pragma unroll
    for (int ks = 0; ks < 4; ++ks) {
      const int kk = ks * 16;
      if constexpr (A_NK && B_NK) {            // MODE 0
        wmma::fragment<wmma::matrix_a, 16, 16, 16, __half, wmma::row_major> af[2];
#pragma unroll
        for (int mt = 0; mt < 2; mt++)
          wmma::load_matrix_sync(af[mt], As + (wm + mt * 16) * 72 + kk, 72);
#pragma unroll
        for (int nt = 0; nt < 4; nt++) {
          wmma::fragment<wmma::matrix_b, 16, 16, 16, __half, wmma::col_major> bf;
          wmma::load_matrix_sync(bf, Bs + (wn + nt * 16) * 72 + kk, 72);
          wmma::mma_sync(c[0][nt], af[0], bf, c[0][nt]);
          wmma::mma_sync(c[1][nt], af[1], bf, c[1][nt]);
        }
      } else if constexpr (A_NK && !B_NK) {    // MODE 1
        wmma::fragment<wmma::matrix_a, 16, 16, 16, __half, wmma::row_major> af[2];
#pragma unroll
        for (int mt = 0; mt < 2; mt++)
          wmma::load_matrix_sync(af[mt], As + (wm + mt * 16) * 72 + kk, 72);
#pragma unroll
        for (int nt = 0; nt < 4; nt++) {
          wmma::fragment<wmma::matrix_b, 16, 16, 16, __half, wmma::row_major> bf;
          wmma::load_matrix_sync(bf, Bs + kk * 136 + wn + nt * 16, 136);
          wmma::mma_sync(c[0][nt], af[0], bf, c[0][nt]);
          wmma::mma_sync(c[1][nt], af[1], bf, c[1][nt]);
        }
      } else {                                 // MODE 2
        wmma::fragment<wmma::matrix_a, 16, 16, 16, __half, wmma::col_major> af[2];
#pragma unroll
        for (int mt = 0; mt < 2; mt++)
          wmma::load_matrix_sync(af[mt], As + kk * 136 + wm + mt * 16, 136);
#pragma unroll
        for (int nt = 0; nt < 4; nt++) {
          wmma::fragment<wmma::matrix_b, 16, 16, 16, __half, wmma::row_major> bf;
          wmma::load_matrix_sync(bf, Bs + kk * 136 + wn + nt * 16, 136);
          wmma::mma_sync(c[0][nt], af[0], bf, c[0][nt]);
          wmma::mma_sync(c[1][nt], af[1], bf, c[1][nt]);
        }
      }
    }
  }
#undef ISSUE
  __syncthreads();   // all warps out of the mainloop before smem reuse

  // ---- stage accumulators to SMEM (compiler-owned layout), plain epilogue
  float* sf = (float*)smem;                 // 128x128 f32 = 64KB
#pragma unroll
  for (int mt = 0; mt < 2; mt++)
#pragma unroll
    for (int nt = 0; nt < 4; nt++)
      wmma::store_matrix_sync(sf + (size_t)(wm + mt * 16) * 128 + wn + nt * 16,
                              c[mt][nt], 128, wmma::mem_row_major);
  __syncthreads();

  const int r = tid >> 1;                   // 0..127
  const int chalf = (tid & 1) * 64;         // 0 or 64
  const int ri = i0 + r;
  const float* srow = sf + (size_t)r * 128 + chalf;

  if (MODE == 0) {
    const float u0 = g_u[b * SEQ + ri] + bias[0];
    __half* erow = g_E + ((size_t)b * SEQ + ri) * 1024 + j0 + chalf;
    float rsum = 0.f;
#pragma unroll
    for (int q = 0; q < 16; ++q) {
      float4 s4 = *(const float4*)(srow + q * 4);
      const int col = j0 + chalf + q * 4;
      float e0 = __expf(tanhf(s4.x + u0 + g_v[b * SEQ + col]));
      float e1 = __expf(tanhf(s4.y + u0 + g_v[b * SEQ + col + 1]));
      float e2 = __expf(tanhf(s4.z + u0 + g_v[b * SEQ + col + 2]));
      float e3 = __expf(tanhf(s4.w + u0 + g_v[b * SEQ + col + 3]));
      rsum += (e0 + e1) + (e2 + e3);
      *(__half2*)(erow + q * 4)     = __floats2half2_rn(e0, e1);
      *(__half2*)(erow + q * 4 + 2) = __floats2half2_rn(e2, e3);
    }
    // pair lanes (tid, tid^1) hold the two halves of row ri
    rsum += __shfl_xor_sync(0xffffffff, rsum, 1);
    if ((tid & 1) == 0)
      g_rpart[(size_t)blockIdx.x * (NB * SEQ) + b * SEQ + ri] = rsum;
  } else {
    const float* scale = (MODE == 1) ? g_rinv : g_cinv;
    const float iv = scale[b * SEQ + ri];
    float4* orow = (float4*)(out + ((size_t)b * SEQ + ri) * 2048 + 1024 + j0 + chalf);
#pragma unroll
    for (int q = 0; q < 16; ++q) {
      float4 s4 = *(const float4*)(srow + q * 4);
      orow[q] = make_float4(s4.x * iv, s4.y * iv, s4.z * iv, s4.w * iv);
    }
  }
}

// ---------------------------------------------------------------------------
// colsum(E) partials over 128-row chunks (coalesced in r)
// ---------------------------------------------------------------------------
__global__ void colsum_part() {
  const int b = blockIdx.z, chunk = blockIdx.y;
  const int r = blockIdx.x * 256 + threadIdx.x;
  const __half* e = g_E + (size_t)b * SEQ * SEQ + (size_t)chunk * 128 * SEQ + r;
  float s = 0.f;
#pragma unroll 8
  for (int l = 0; l < 128; l++) s += __half2float(e[(size_t)l * SEQ]);
  g_cpart[(b * 8 + chunk) * SEQ + r] = s;
}

// ---------------------------------------------------------------------------
// finalize: rinv from 8 row partials, cinv from 8 col partials
// ---------------------------------------------------------------------------
__global__ void finalize_kernel() {
  const int idx = blockIdx.x * 256 + threadIdx.x;   // b*SEQ + x
  const int b = idx >> 10;
  float sr = 0.f, sc = 0.f;
#pragma unroll
  for (int j = 0; j < 8; j++) sr += g_rpart[(size_t)j * (NB * SEQ) + idx];
#pragma unroll
  for (int c = 0; c < 8; c++) sc += g_cpart[(b * 8 + c) * SEQ + (idx & 1023)];
  g_rinv[idx] = 1.0f / sr;
  g_cinv[idx] = 1.0f / sc;
}

// ---------------------------------------------------------------------------
extern "C" void kernel_launch(void* const* d_in, const int* in_sizes, int n_in,
                              void* d_out, int out_size) {
  const float* lhs = (const float*)d_in[0];
  const float* rhs = (const float*)d_in[1];
  const float* w   = (const float*)d_in[2];
  const float* bp  = (const float*)d_in[3];
  float* out = (float*)d_out;

  cudaFuncSetAttribute(mma_gemm<0>, cudaFuncAttributeMaxDynamicSharedMemorySize, GSMEM);
  cudaFuncSetAttribute(mma_gemm<1>, cudaFuncAttributeMaxDynamicSharedMemorySize, GSMEM);
  cudaFuncSetAttribute(mma_gemm<2>, cudaFuncAttributeMaxDynamicSharedMemorySize, GSMEM);

  fuse_kernel<<<NB * SEQ, 256>>>((const float4*)lhs, (const float4*)rhs,
                                 (const float4*)w, (float4*)out);

  mma_gemm<0><<<dim3(8, 8, NB), 256, GSMEM>>>(bp, out);        // -> g_E + rpart
  colsum_part<<<dim3(4, 8, NB), 256>>>();
  finalize_kernel<<<NB * SEQ / 256, 256>>>();                   // rinv + cinv

  mma_gemm<1><<<dim3(8, 8, NB), 256, GSMEM>>>(bp, out);         // lhs attn
  mma_gemm<2><<<dim3(8, 8, NB), 256, GSMEM>>>(bp, out + OFF2);  // rhs attn
}